// round 17
// baseline (speedup 1.0000x reference)
#include <cuda_runtime.h>
#include <cuda_fp16.h>
#include <mma.h>
#include <math.h>
#include <stdint.h>

using namespace nvcuda;

// Problem constants
#define SEQ    2048
#define DMODEL 4096
#define NHEAD  32
#define NKV    8
#define HD     128
#define KVD    (NKV * HD)   // 1024

// ---------------------------------------------------------------------------
// Scratch (device globals: allocation-free)
// ---------------------------------------------------------------------------
__device__ float  g_Q[SEQ * DMODEL];           // fp32 Q (rope in-place; flash reads)
__device__ float  g_K[SEQ * KVD];              // fp32 K (pre-rope)
__device__ float  g_V[SEQ * KVD];              // fp32 V
__device__ __half g_K16[SEQ * KVD];            // roped K, fp16, [s][kv]
__device__ __half g_V16T[KVD * SEQ];           // V transposed, fp16, [kv][s]
__device__ __half g_x16[SEQ * DMODEL];
__device__ __half g_O16[SEQ * DMODEL];         // flash output, fp16
__device__ __half g_Wq16[DMODEL * DMODEL];
__device__ __half g_Wk16[DMODEL * KVD];
__device__ __half g_Wv16[DMODEL * KVD];
__device__ __half g_Wo16[DMODEL * DMODEL];

// ---------------------------------------------------------------------------
// PTX helpers
// ---------------------------------------------------------------------------
__device__ __forceinline__ void cp_async16(void* dst, const void* src) {
    unsigned s = (unsigned)__cvta_generic_to_shared(dst);
    asm volatile("cp.async.cg.shared.global [%0], [%1], 16;" :: "r"(s), "l"(src));
}
__device__ __forceinline__ void cp_commit() {
    asm volatile("cp.async.commit_group;");
}
__device__ __forceinline__ void mma_f16(float* c, const unsigned* a, unsigned b0, unsigned b1) {
    asm volatile(
        "mma.sync.aligned.m16n8k16.row.col.f32.f16.f16.f32 "
        "{%0,%1,%2,%3}, {%4,%5,%6,%7}, {%8,%9}, {%0,%1,%2,%3};"
        : "+f"(c[0]), "+f"(c[1]), "+f"(c[2]), "+f"(c[3])
        : "r"(a[0]), "r"(a[1]), "r"(a[2]), "r"(a[3]), "r"(b0), "r"(b1));
}
__device__ __forceinline__ unsigned packh2(float a, float b) {
    __half2 h = __floats2half2_rn(a, b);
    return *reinterpret_cast<unsigned*>(&h);
}

// ---------------------------------------------------------------------------
// Bulk fp32 -> fp16 conversion
// ---------------------------------------------------------------------------
__global__ void f32_to_f16(const float* __restrict__ in, __half* __restrict__ out, int n)
{
    int i = (blockIdx.x * blockDim.x + threadIdx.x) * 8;
    if (i >= n) return;
    float4 a = *reinterpret_cast<const float4*>(in + i);
    float4 b = *reinterpret_cast<const float4*>(in + i + 4);
    __half2 h[4];
    h[0] = __floats2half2_rn(a.x, a.y);
    h[1] = __floats2half2_rn(a.z, a.w);
    h[2] = __floats2half2_rn(b.x, b.y);
    h[3] = __floats2half2_rn(b.z, b.w);
    *reinterpret_cast<uint4*>(out + i) = *reinterpret_cast<uint4*>(h);
}

// ---------------------------------------------------------------------------
// V transpose + convert: V[S][KVD] fp32 -> V16T[KVD][S] fp16
// ---------------------------------------------------------------------------
__global__ void v_transp16(const float* __restrict__ in, __half* __restrict__ out)
{
    __shared__ float t[32][33];
    int c0 = blockIdx.x * 32, s0 = blockIdx.y * 32;
    int tx = threadIdx.x, ty = threadIdx.y;   // 32 x 8
#pragma unroll
    for (int i = 0; i < 32; i += 8)
        t[ty + i][tx] = in[(size_t)(s0 + ty + i) * KVD + c0 + tx];
    __syncthreads();
#pragma unroll
    for (int i = 0; i < 32; i += 8)
        out[(size_t)(c0 + ty + i) * SEQ + s0 + tx] = __float2half(t[tx][ty + i]);
}

// ---------------------------------------------------------------------------
// fp16 GEMM v2: C[M,N](f32) = A[M,K] @ B[K,N], all row-major.
// 128x128 CTA tile, BK=32, 3-stage cp.async, 4 warps (2x2), warp tile 64x64
// (4x4 wmma m16n16k16 frags -> mma:ldsm ratio 2.0). 128 threads, 2 CTAs/SM.
// ---------------------------------------------------------------------------
typedef wmma::fragment<wmma::matrix_a, 16, 16, 16, __half, wmma::row_major> HFragA;
typedef wmma::fragment<wmma::matrix_b, 16, 16, 16, __half, wmma::row_major> HFragB;
typedef wmma::fragment<wmma::accumulator, 16, 16, 16, float> HFragC;

struct GemmHSmem {
    __half As[3][128][40];   // row stride 80B
    __half Bs[3][32][136];   // row stride 272B
};

__global__ __launch_bounds__(128)
void gemm_f16_nn(const __half* __restrict__ A, const __half* __restrict__ B,
                 float* __restrict__ C, int K, int lda, int ldb, int ldc)
{
    extern __shared__ char smem_raw[];
    GemmHSmem& sm = *reinterpret_cast<GemmHSmem*>(smem_raw);
    const int tid = threadIdx.x;
    const int wid = tid >> 5;
    const int wm = wid >> 1, wn = wid & 1;      // 2x2 warp grid
    const int brow = blockIdx.y, bcol = blockIdx.x;
    const __half* Ag = A + (size_t)(brow * 128) * lda;
    const __half* Bg = B + bcol * 128;

    HFragC acc[4][4];
#pragma unroll
    for (int i = 0; i < 4; i++)
#pragma unroll
        for (int j = 0; j < 4; j++) wmma::fill_fragment(acc[i][j], 0.0f);

    // Stage K-slab k0 into buffer s. A: 128x32 halves = 512 chunks;
    // B: 32x128 halves = 512 chunks; 128 threads x 4 iters each.
    auto stage = [&](int s, int k0) {
#pragma unroll
        for (int i = 0; i < 4; i++) {
            int ch = tid + 128 * i;
            int r = ch >> 2, c = (ch & 3) * 8;
            cp_async16(&sm.As[s][r][c], Ag + (size_t)r * lda + k0 + c);
        }
#pragma unroll
        for (int i = 0; i < 4; i++) {
            int ch = tid + 128 * i;
            int r = ch >> 4, c = (ch & 15) * 8;
            cp_async16(&sm.Bs[s][r][c], Bg + (size_t)(k0 + r) * ldb + c);
        }
        cp_commit();
    };

    const int nt = K / 32;
    stage(0, 0);
    stage(1, 32);
    for (int t = 0; t < nt; t++) {
        if (t + 2 < nt) stage((t + 2) % 3, (t + 2) * 32);
        const int pending = (t + 2 < nt) ? 2 : ((t + 1 < nt) ? 1 : 0);
        if (pending == 2)      asm volatile("cp.async.wait_group 2;");
        else if (pending == 1) asm volatile("cp.async.wait_group 1;");
        else                   asm volatile("cp.async.wait_group 0;");
        __syncthreads();
        const int s = t % 3;
#pragma unroll
        for (int kk = 0; kk < 32; kk += 16) {
            HFragA fa[4];
            HFragB fb[4];
#pragma unroll
            for (int i = 0; i < 4; i++)
                wmma::load_matrix_sync(fa[i], &sm.As[s][wm * 64 + i * 16][kk], 40);
#pragma unroll
            for (int j = 0; j < 4; j++)
                wmma::load_matrix_sync(fb[j], &sm.Bs[s][kk][wn * 64 + j * 16], 136);
#pragma unroll
            for (int i = 0; i < 4; i++)
#pragma unroll
                for (int j = 0; j < 4; j++)
                    wmma::mma_sync(acc[i][j], fa[i], fb[j], acc[i][j]);
        }
        __syncthreads();
    }
#pragma unroll
    for (int i = 0; i < 4; i++)
#pragma unroll
        for (int j = 0; j < 4; j++)
            wmma::store_matrix_sync(
                C + (size_t)(brow * 128 + wm * 64 + i * 16) * ldc + bcol * 128 + wn * 64 + j * 16,
                acc[i][j], ldc, wmma::mem_row_major);
}

// ---------------------------------------------------------------------------
// Flash attention (causal, GQA) — unchanged from passing R14 kernel.
// ---------------------------------------------------------------------------
struct FlashSmem {
    __half Ks[64][136];
    __half Vt[128][72];
    __half Ps[64][72];
};

__global__ __launch_bounds__(128)
void flash_attn(const float* __restrict__ Q, const __half* __restrict__ K16,
                const __half* __restrict__ V16T, __half* __restrict__ O16)
{
    extern __shared__ char smem_raw[];
    FlashSmem& sm = *reinterpret_cast<FlashSmem*>(smem_raw);

    const int h   = blockIdx.x;
    const int qb  = gridDim.y - 1 - blockIdx.y;
    const int kvh = h >> 2;
    const int warp = threadIdx.x >> 5;
    const int lane = threadIdx.x & 31;
    const int lr = lane >> 2;
    const int lc = lane & 3;

    unsigned qa[8][4];
    {
        const float scale = 0.08838834764831845f;
        const float* Qb = Q + (size_t)(qb * 64 + warp * 16) * DMODEL + h * HD;
#pragma unroll
        for (int kt = 0; kt < 8; kt++) {
            int c0 = kt * 16 + 2 * lc;
            qa[kt][0] = packh2(Qb[(size_t)lr * DMODEL + c0] * scale,
                               Qb[(size_t)lr * DMODEL + c0 + 1] * scale);
            qa[kt][1] = packh2(Qb[(size_t)(lr + 8) * DMODEL + c0] * scale,
                               Qb[(size_t)(lr + 8) * DMODEL + c0 + 1] * scale);
            qa[kt][2] = packh2(Qb[(size_t)lr * DMODEL + c0 + 8] * scale,
                               Qb[(size_t)lr * DMODEL + c0 + 9] * scale);
            qa[kt][3] = packh2(Qb[(size_t)(lr + 8) * DMODEL + c0 + 8] * scale,
                               Qb[(size_t)(lr + 8) * DMODEL + c0 + 9] * scale);
        }
    }

    float oacc[16][4];
#pragma unroll
    for (int j = 0; j < 16; j++)
#pragma unroll
        for (int e = 0; e < 4; e++) oacc[j][e] = 0.0f;
    float m0 = -1e30f, m1 = -1e30f, l0 = 0.0f, l1 = 0.0f;

    for (int kb = 0; kb <= qb; kb++) {
        __syncthreads();
        {
            const __half* Kt = K16 + (size_t)(kb * 64) * KVD + kvh * HD;
            const __half* Vg = V16T + (size_t)(kvh * HD) * SEQ + kb * 64;
#pragma unroll
            for (int i = 0; i < 8; i++) {
                int ch = threadIdx.x + 128 * i;
                int kr = ch >> 4, kj = ch & 15;
                cp_async16(&sm.Ks[kr][kj * 8], Kt + (size_t)kr * KVD + kj * 8);
                int vr = ch >> 3, vj = ch & 7;
                cp_async16(&sm.Vt[vr][vj * 8], Vg + (size_t)vr * SEQ + vj * 8);
            }
            cp_commit();
            asm volatile("cp.async.wait_group 0;");
        }
        __syncthreads();

        float sacc[8][4];
#pragma unroll
        for (int j = 0; j < 8; j++)
#pragma unroll
            for (int e = 0; e < 4; e++) sacc[j][e] = 0.0f;
#pragma unroll
        for (int kt = 0; kt < 8; kt++) {
            const int c0 = kt * 16 + 2 * lc;
#pragma unroll
            for (int j = 0; j < 8; j++) {
                unsigned b0 = *reinterpret_cast<const unsigned*>(&sm.Ks[j * 8 + lr][c0]);
                unsigned b1 = *reinterpret_cast<const unsigned*>(&sm.Ks[j * 8 + lr][c0 + 8]);
                mma_f16(sacc[j], qa[kt], b0, b1);
            }
        }

        if (kb == qb) {
            const int r0 = warp * 16 + lr, r1 = r0 + 8;
#pragma unroll
            for (int j = 0; j < 8; j++) {
                int c0 = j * 8 + lc * 2;
                if (c0     > r0) sacc[j][0] = -1e30f;
                if (c0 + 1 > r0) sacc[j][1] = -1e30f;
                if (c0     > r1) sacc[j][2] = -1e30f;
                if (c0 + 1 > r1) sacc[j][3] = -1e30f;
            }
        }

        float mx0 = -1e30f, mx1 = -1e30f;
#pragma unroll
        for (int j = 0; j < 8; j++) {
            mx0 = fmaxf(mx0, fmaxf(sacc[j][0], sacc[j][1]));
            mx1 = fmaxf(mx1, fmaxf(sacc[j][2], sacc[j][3]));
        }
        mx0 = fmaxf(mx0, __shfl_xor_sync(0xffffffffu, mx0, 1));
        mx0 = fmaxf(mx0, __shfl_xor_sync(0xffffffffu, mx0, 2));
        mx1 = fmaxf(mx1, __shfl_xor_sync(0xffffffffu, mx1, 1));
        mx1 = fmaxf(mx1, __shfl_xor_sync(0xffffffffu, mx1, 2));
        const float mn0 = fmaxf(m0, mx0), mn1 = fmaxf(m1, mx1);
        const float al0 = __expf(m0 - mn0), al1 = __expf(m1 - mn1);
        m0 = mn0; m1 = mn1;

        float s0 = 0.0f, s1 = 0.0f;
        const int prow = warp * 16 + lr;
#pragma unroll
        for (int j = 0; j < 8; j++) {
            float p0 = __expf(sacc[j][0] - m0);
            float p1 = __expf(sacc[j][1] - m0);
            float p2 = __expf(sacc[j][2] - m1);
            float p3 = __expf(sacc[j][3] - m1);
            s0 += p0 + p1;
            s1 += p2 + p3;
            *reinterpret_cast<unsigned*>(&sm.Ps[prow][j * 8 + lc * 2])     = packh2(p0, p1);
            *reinterpret_cast<unsigned*>(&sm.Ps[prow + 8][j * 8 + lc * 2]) = packh2(p2, p3);
        }
        s0 += __shfl_xor_sync(0xffffffffu, s0, 1);
        s0 += __shfl_xor_sync(0xffffffffu, s0, 2);
        s1 += __shfl_xor_sync(0xffffffffu, s1, 1);
        s1 += __shfl_xor_sync(0xffffffffu, s1, 2);
        l0 = l0 * al0 + s0;
        l1 = l1 * al1 + s1;

#pragma unroll
        for (int j = 0; j < 16; j++) {
            oacc[j][0] *= al0; oacc[j][1] *= al0;
            oacc[j][2] *= al1; oacc[j][3] *= al1;
        }
        __syncwarp();

#pragma unroll
        for (int kt = 0; kt < 4; kt++) {
            const int c0 = kt * 16 + 2 * lc;
            unsigned pa[4];
            pa[0] = *reinterpret_cast<const unsigned*>(&sm.Ps[warp * 16 + lr][c0]);
            pa[1] = *reinterpret_cast<const unsigned*>(&sm.Ps[warp * 16 + lr + 8][c0]);
            pa[2] = *reinterpret_cast<const unsigned*>(&sm.Ps[warp * 16 + lr][c0 + 8]);
            pa[3] = *reinterpret_cast<const unsigned*>(&sm.Ps[warp * 16 + lr + 8][c0 + 8]);
#pragma unroll
            for (int j = 0; j < 16; j++) {
                unsigned b0 = *reinterpret_cast<const unsigned*>(&sm.Vt[j * 8 + lr][c0]);
                unsigned b1 = *reinterpret_cast<const unsigned*>(&sm.Vt[j * 8 + lr][c0 + 8]);
                mma_f16(oacc[j], pa, b0, b1);
            }
        }
    }

    const float r0 = 1.0f / l0, r1 = 1.0f / l1;
    __half* Ob = O16 + (size_t)(qb * 64 + warp * 16) * DMODEL + h * HD;
#pragma unroll
    for (int j = 0; j < 16; j++) {
        *reinterpret_cast<unsigned*>(&Ob[(size_t)lr * DMODEL + j * 8 + lc * 2]) =
            packh2(oacc[j][0] * r0, oacc[j][1] * r0);
        *reinterpret_cast<unsigned*>(&Ob[(size_t)(lr + 8) * DMODEL + j * 8 + lc * 2]) =
            packh2(oacc[j][2] * r1, oacc[j][3] * r1);
    }
}

// ---------------------------------------------------------------------------
// RoPE: Q fp32 in-place; K fp32 -> fp16 out.
// ---------------------------------------------------------------------------
__global__ void rope_q(float* __restrict__ X, int total)
{
    int idx = blockIdx.x * blockDim.x + threadIdx.x;
    if (idx >= total) return;
    int p = idx & 63;
    int t = idx >> 6;
    int h = t % NHEAD;
    int s = t / NHEAD;
    float inv = exp2f(-(float)p * (18.931568569324174f / 64.0f));
    float sv, cv;
    sincosf((float)s * inv, &sv, &cv);
    float* q = X + (size_t)s * DMODEL + h * HD + 2 * p;
    float x0 = q[0], x1 = q[1];
    q[0] = x0 * cv - x1 * sv;
    q[1] = x0 * sv + x1 * cv;
}

__global__ void rope_k16(const float* __restrict__ Kin, __half* __restrict__ Kout, int total)
{
    int idx = blockIdx.x * blockDim.x + threadIdx.x;
    if (idx >= total) return;
    int p = idx & 63;
    int t = idx >> 6;
    int h = t % NKV;
    int s = t / NKV;
    float inv = exp2f(-(float)p * (18.931568569324174f / 64.0f));
    float sv, cv;
    sincosf((float)s * inv, &sv, &cv);
    const float* k = Kin + (size_t)s * KVD + h * HD + 2 * p;
    float x0 = k[0], x1 = k[1];
    *reinterpret_cast<unsigned*>(Kout + (size_t)s * KVD + h * HD + 2 * p) =
        packh2(x0 * cv - x1 * sv, x0 * sv + x1 * cv);
}

// ---------------------------------------------------------------------------
// Launch
// ---------------------------------------------------------------------------
extern "C" void kernel_launch(void* const* d_in, const int* in_sizes, int n_in,
                              void* d_out, int out_size)
{
    const float* x  = (const float*)d_in[0];
    const float* Wq = (const float*)d_in[1];
    const float* Wk = (const float*)d_in[2];
    const float* Wv = (const float*)d_in[3];
    const float* Wo = (const float*)d_in[4];
    float* out = (float*)d_out;

    float *Q, *K, *V;
    __half *K16, *V16T, *x16, *O16, *Wq16, *Wk16, *Wv16, *Wo16;
    cudaGetSymbolAddress((void**)&Q, g_Q);
    cudaGetSymbolAddress((void**)&K, g_K);
    cudaGetSymbolAddress((void**)&V, g_V);
    cudaGetSymbolAddress((void**)&K16, g_K16);
    cudaGetSymbolAddress((void**)&V16T, g_V16T);
    cudaGetSymbolAddress((void**)&x16, g_x16);
    cudaGetSymbolAddress((void**)&O16, g_O16);
    cudaGetSymbolAddress((void**)&Wq16, g_Wq16);
    cudaGetSymbolAddress((void**)&Wk16, g_Wk16);
    cudaGetSymbolAddress((void**)&Wv16, g_Wv16);
    cudaGetSymbolAddress((void**)&Wo16, g_Wo16);

    cudaFuncSetAttribute(gemm_f16_nn, cudaFuncAttributeMaxDynamicSharedMemorySize,
                         (int)sizeof(GemmHSmem));
    cudaFuncSetAttribute(flash_attn, cudaFuncAttributeMaxDynamicSharedMemorySize,
                         (int)sizeof(FlashSmem));

    // fp32 -> fp16 conversions (x and weights)
    {
        const int nx = SEQ * DMODEL;
        const int nq = DMODEL * DMODEL;
        const int nk = DMODEL * KVD;
        f32_to_f16<<<(nx / 8 + 255) / 256, 256>>>(x,  x16,  nx);
        f32_to_f16<<<(nq / 8 + 255) / 256, 256>>>(Wq, Wq16, nq);
        f32_to_f16<<<(nk / 8 + 255) / 256, 256>>>(Wk, Wk16, nk);
        f32_to_f16<<<(nk / 8 + 255) / 256, 256>>>(Wv, Wv16, nk);
        f32_to_f16<<<(nq / 8 + 255) / 256, 256>>>(Wo, Wo16, nq);
    }

    // QKV projections (fp16 HMMA, fp32 accumulate)
    gemm_f16_nn<<<dim3(DMODEL / 128, SEQ / 128), 128, sizeof(GemmHSmem)>>>(
        x16, Wq16, Q, DMODEL, DMODEL, DMODEL, DMODEL);
    gemm_f16_nn<<<dim3(KVD / 128, SEQ / 128), 128, sizeof(GemmHSmem)>>>(
        x16, Wk16, K, DMODEL, DMODEL, KVD, KVD);
    gemm_f16_nn<<<dim3(KVD / 128, SEQ / 128), 128, sizeof(GemmHSmem)>>>(
        x16, Wv16, V, DMODEL, DMODEL, KVD, KVD);

    // RoPE (Q fp32 in-place, K -> fp16) + V -> fp16 transposed
    {
        int totq = SEQ * NHEAD * (HD / 2);
        rope_q<<<(totq + 255) / 256, 256>>>(Q, totq);
        int totk = SEQ * NKV * (HD / 2);
        rope_k16<<<(totk + 255) / 256, 256>>>(K, K16, totk);
        v_transp16<<<dim3(KVD / 32, SEQ / 32), dim3(32, 8)>>>(V, V16T);
    }

    // Fused causal flash attention (fp16 tensor path) -> O16
    flash_attn<<<dim3(NHEAD, SEQ / 64), 128, sizeof(FlashSmem)>>>(Q, K16, V16T, O16);

    // Output projection
    gemm_f16_nn<<<dim3(DMODEL / 128, SEQ / 128), 128, sizeof(GemmHSmem)>>>(
        O16, Wo16, out, DMODEL, DMODEL, DMODEL, DMODEL);
}